// round 14
// baseline (speedup 1.0000x reference)
#include <cuda_runtime.h>
#include <cuda_bf16.h>
#include <cuda_fp16.h>
#include <cstdint>

// GCN 2-layer, CSR gather formulation with pre-scaled fp16 rows.
// R11 fork schedule + GEMM2 fused into the layer-1 aggregation (k_agg1f).

#define NMAX   100000
#define EMAX   1600000
#define IN_CH  128
#define HID    64
#define OUTC   32

typedef unsigned long long ull;

__device__ int    g_cnt[NMAX];           // in-degree (no self loop)
__device__ int    g_part[512];           // block partials -> inclusive prefix
__device__ int    g_off[NMAX + 1];       // CSR offsets
__device__ int    g_cur[NMAX];           // scatter cursors
__device__ int    g_csrc[EMAX];          // CSR src lists grouped by dst
__device__ float  g_dis[NMAX];           // deg^{-1/2} (deg incl self loop)
__device__ __half g_h1h[NMAX * HID];     // dis-scaled x@W1, fp16
__device__ __half g_h2h[NMAX * OUTC];    // dis-scaled relu(agg1)@W2, fp16

__device__ __forceinline__ uint32_t to_tf32(float f) {
    uint32_t r;
    asm("cvt.rna.tf32.f32 %0, %1;" : "=r"(r) : "f"(f));
    return r;
}

__device__ __forceinline__ void mma_tf32(float* d, const uint32_t* a, const uint32_t* b) {
    asm("mma.sync.aligned.m16n8k8.row.col.f32.tf32.tf32.f32 "
        "{%0,%1,%2,%3}, {%4,%5,%6,%7}, {%8,%9}, {%0,%1,%2,%3};"
        : "+f"(d[0]), "+f"(d[1]), "+f"(d[2]), "+f"(d[3])
        : "r"(a[0]), "r"(a[1]), "r"(a[2]), "r"(a[3]), "r"(b[0]), "r"(b[1]));
}

// ---------------- CSR build ----------------

__global__ void k_zero(int n) {
    int i = blockIdx.x * blockDim.x + threadIdx.x;
    if (i < n) g_cnt[i] = 0;
}

__global__ void k_count(const int* __restrict__ ei, int E) {
    int e = blockIdx.x * blockDim.x + threadIdx.x;
    if (e < E) atomicAdd(&g_cnt[ei[E + e]], 1);
}

__global__ void k_dis(int n) {
    int i = blockIdx.x * blockDim.x + threadIdx.x;
    if (i < n) g_dis[i] = rsqrtf((float)(g_cnt[i] + 1));
}

// scan pass 1: per-block sums of g_cnt (256 per block)
__global__ __launch_bounds__(256) void k_scan1(int n) {
    __shared__ int s[256];
    int t = threadIdx.x;
    int i = blockIdx.x * 256 + t;
    s[t] = (i < n) ? g_cnt[i] : 0;
    __syncthreads();
#pragma unroll
    for (int st = 128; st > 0; st >>= 1) {
        if (t < st) s[t] += s[t + st];
        __syncthreads();
    }
    if (t == 0) g_part[blockIdx.x] = s[0];
}

// scan pass 2: single block 512 thr, warp-shuffle inclusive scan of partials
__global__ __launch_bounds__(512) void k_scan2(int nb) {
    __shared__ int warp_sum[16];
    int t = threadIdx.x;
    int lane = t & 31, w = t >> 5;
    int v = (t < nb) ? g_part[t] : 0;
#pragma unroll
    for (int ofs = 1; ofs < 32; ofs <<= 1) {
        int u = __shfl_up_sync(0xffffffffu, v, ofs);
        if (lane >= ofs) v += u;
    }
    if (lane == 31) warp_sum[w] = v;
    __syncthreads();
    if (w == 0) {
        int ws = (lane < 16) ? warp_sum[lane] : 0;
#pragma unroll
        for (int ofs = 1; ofs < 16; ofs <<= 1) {
            int u = __shfl_up_sync(0xffffffffu, ws, ofs);
            if (lane >= ofs) ws += u;
        }
        if (lane < 16) warp_sum[lane] = ws;
    }
    __syncthreads();
    if (w > 0) v += warp_sum[w - 1];
    g_part[t] = v;
}

// scan pass 3: offsets = block base + in-block exclusive scan
__global__ __launch_bounds__(256) void k_scan3(int n) {
    __shared__ int s[256];
    int t = threadIdx.x;
    int i = blockIdx.x * 256 + t;
    int c = (i < n) ? g_cnt[i] : 0;
    s[t] = c;
    __syncthreads();
#pragma unroll
    for (int ofs = 1; ofs < 256; ofs <<= 1) {
        int v = (t >= ofs) ? s[t - ofs] : 0;
        __syncthreads();
        s[t] += v;
        __syncthreads();
    }
    int basep = blockIdx.x ? g_part[blockIdx.x - 1] : 0;
    if (i < n) {
        int off = basep + s[t] - c;
        g_off[i] = off;
        g_cur[i] = off;
        if (i == n - 1) g_off[n] = basep + s[t];
    }
}

__global__ void k_scatter(const int* __restrict__ ei, int E) {
    int e = blockIdx.x * blockDim.x + threadIdx.x;
    if (e < E) {
        int s = ei[e];
        int d = ei[E + e];
        int pos = atomicAdd(&g_cur[d], 1);
        g_csrc[pos] = s;
    }
}

// ---------------- GEMM1 (tf32 tensor core): h1h = fp16(dis * x@W1) -------
// CTA: 128 nodes x 64 ch, K chunked by 32. 8 warps 4(M)x2(N), warp 32x32.

#define KCT 32

__global__ __launch_bounds__(256) void k_gemm1(const float* __restrict__ x,
                                               const float* __restrict__ W1,
                                               int n) {
    __shared__ uint32_t sA[8 * 4 * 32 * 4];   // 16 KB
    __shared__ uint32_t sB[8 * 4 * 32 * 2];   // 8 KB

    int tid = threadIdx.x;
    int lane = tid & 31;
    int wid = tid >> 5;
    int warp_m = wid & 3;
    int warp_n = wid >> 2;
    int base = blockIdx.x * 128;

    float acc[2][4][4];
#pragma unroll
    for (int fm = 0; fm < 2; fm++)
#pragma unroll
        for (int fn = 0; fn < 4; fn++)
#pragma unroll
            for (int r = 0; r < 4; r++) acc[fm][fn][r] = 0.f;

    for (int kc = 0; kc < IN_CH; kc += KCT) {
        __syncthreads();
#pragma unroll
        for (int i = 0; i < 4; i++) {
            int f = tid + 256 * i;
            int node = f >> 3;
            int q = f & 7;
            int gn = base + node;
            float4 v = make_float4(0.f, 0.f, 0.f, 0.f);
            if (gn < n) v = reinterpret_cast<const float4*>(x + gn * IN_CH + kc)[q];
            float vv[4] = {v.x, v.y, v.z, v.w};
            int mt = node >> 4, mm = node & 15;
#pragma unroll
            for (int j = 0; j < 4; j++) {
                int k = 4 * q + j;
                int kstep = k >> 3, kk = k & 7;
                int lt = ((mm & 7) << 2) | (kk & 3);
                int idx = (mm >> 3) | ((kk >> 2) << 1);
                sA[(((mt << 2) | kstep) << 7) + (lt << 2) + idx] = to_tf32(vv[j]);
            }
        }
#pragma unroll
        for (int i = 0; i < 2; i++) {
            int f = tid + 256 * i;
            int kr = f >> 4;
            int qc = f & 15;
            float4 w = reinterpret_cast<const float4*>(W1 + (kc + kr) * HID)[qc];
            float ww[4] = {w.x, w.y, w.z, w.w};
            int kstep = kr >> 3, kk = kr & 7;
#pragma unroll
            for (int j = 0; j < 4; j++) {
                int c = 4 * qc + j;
                int nt = c >> 3, nn = c & 7;
                int lt = (nn << 2) | (kk & 3);
                int idx = kk >> 2;
                sB[(((nt << 2) | kstep) << 6) + (lt << 1) + idx] = to_tf32(ww[j]);
            }
        }
        __syncthreads();

#pragma unroll
        for (int kstep = 0; kstep < 4; kstep++) {
            uint32_t a[2][4];
#pragma unroll
            for (int fm = 0; fm < 2; fm++) {
                int mt = warp_m * 2 + fm;
                uint4 v = *reinterpret_cast<const uint4*>(
                    sA + (((mt << 2) | kstep) << 7) + (lane << 2));
                a[fm][0] = v.x; a[fm][1] = v.y; a[fm][2] = v.z; a[fm][3] = v.w;
            }
            uint32_t b[4][2];
#pragma unroll
            for (int fn = 0; fn < 4; fn++) {
                int nt = warp_n * 4 + fn;
                uint2 v = *reinterpret_cast<const uint2*>(
                    sB + (((nt << 2) | kstep) << 6) + (lane << 1));
                b[fn][0] = v.x; b[fn][1] = v.y;
            }
#pragma unroll
            for (int fm = 0; fm < 2; fm++)
#pragma unroll
                for (int fn = 0; fn < 4; fn++)
                    mma_tf32(acc[fm][fn], a[fm], b[fn]);
        }
    }

    int g = lane >> 2, t4 = lane & 3;
#pragma unroll
    for (int fm = 0; fm < 2; fm++) {
#pragma unroll
        for (int r = 0; r < 2; r++) {
            int m = base + warp_m * 32 + fm * 16 + g + r * 8;
            if (m >= n) continue;
            float ds = g_dis[m];
#pragma unroll
            for (int fn = 0; fn < 4; fn++) {
                int nn = warp_n * 32 + fn * 8 + t4 * 2;
                float c0 = acc[fm][fn][2 * r] * ds;
                float c1 = acc[fm][fn][2 * r + 1] * ds;
                *reinterpret_cast<__half2*>(g_h1h + m * HID + nn) =
                    __floats2half2_rn(c0, c1);
            }
        }
    }
}

// ---------------- fused layer-1 aggregation + GEMM2 ----------------------
// Per dst warp: gather sum_s h1h[s] + h1h[d]; r = relu(sum*dd + b1);
// then in-warp GEMV: h2h[d][c] = fp16( dd * sum_k r[k]*W2[k][c] ).
// W2 transposed in smem [c][k], stride 68 (conflict-free LDS.128).

__global__ __launch_bounds__(256) void k_agg1f(const float* __restrict__ b1,
                                               const float* __restrict__ W2,
                                               int n) {
    __shared__ float sW2T[32 * 68];     // 8.7 KB
    __shared__ float sbuf[8][68];       // per-warp relu'd row (64 + pad)

    int tid = threadIdx.x;
    int lane = tid & 31, w = tid >> 5;

    for (int i = tid; i < HID * OUTC; i += 256) {
        int k = i >> 5, c = i & 31;
        sW2T[c * 68 + k] = W2[k * OUTC + c];
    }
    __syncthreads();

    int d = (blockIdx.x * 256 + tid) >> 5;
    if (d >= n) return;
    int lo = g_off[d], hi = g_off[d + 1];
    float dd = g_dis[d];

    float2 acc = __half22float2(
        reinterpret_cast<const __half2*>(g_h1h + d * HID)[lane]);

    for (int jb = lo; jb < hi; jb += 32) {
        int myidx = (jb + lane < hi) ? g_csrc[jb + lane] : 0;
        int cnt = min(32, hi - jb);
        int kk = 0;
        for (; kk + 8 <= cnt; kk += 8) {
            int s0 = __shfl_sync(0xffffffffu, myidx, kk + 0);
            int s1 = __shfl_sync(0xffffffffu, myidx, kk + 1);
            int s2 = __shfl_sync(0xffffffffu, myidx, kk + 2);
            int s3 = __shfl_sync(0xffffffffu, myidx, kk + 3);
            int s4 = __shfl_sync(0xffffffffu, myidx, kk + 4);
            int s5 = __shfl_sync(0xffffffffu, myidx, kk + 5);
            int s6 = __shfl_sync(0xffffffffu, myidx, kk + 6);
            int s7 = __shfl_sync(0xffffffffu, myidx, kk + 7);
            __half2 v0 = reinterpret_cast<const __half2*>(g_h1h + s0 * HID)[lane];
            __half2 v1 = reinterpret_cast<const __half2*>(g_h1h + s1 * HID)[lane];
            __half2 v2 = reinterpret_cast<const __half2*>(g_h1h + s2 * HID)[lane];
            __half2 v3 = reinterpret_cast<const __half2*>(g_h1h + s3 * HID)[lane];
            __half2 v4 = reinterpret_cast<const __half2*>(g_h1h + s4 * HID)[lane];
            __half2 v5 = reinterpret_cast<const __half2*>(g_h1h + s5 * HID)[lane];
            __half2 v6 = reinterpret_cast<const __half2*>(g_h1h + s6 * HID)[lane];
            __half2 v7 = reinterpret_cast<const __half2*>(g_h1h + s7 * HID)[lane];
            float2 f0 = __half22float2(v0), f1 = __half22float2(v1);
            float2 f2 = __half22float2(v2), f3 = __half22float2(v3);
            float2 f4 = __half22float2(v4), f5 = __half22float2(v5);
            float2 f6 = __half22float2(v6), f7 = __half22float2(v7);
            acc.x += ((f0.x + f1.x) + (f2.x + f3.x)) + ((f4.x + f5.x) + (f6.x + f7.x));
            acc.y += ((f0.y + f1.y) + (f2.y + f3.y)) + ((f4.y + f5.y) + (f6.y + f7.y));
        }
        for (; kk < cnt; kk++) {
            int s0 = __shfl_sync(0xffffffffu, myidx, kk);
            float2 f0 = __half22float2(
                reinterpret_cast<const __half2*>(g_h1h + s0 * HID)[lane]);
            acc.x += f0.x;
            acc.y += f0.y;
        }
    }

    float2 bb = reinterpret_cast<const float2*>(b1)[lane];
    float rx = fmaxf(acc.x * dd + bb.x, 0.f);
    float ry = fmaxf(acc.y * dd + bb.y, 0.f);
    *reinterpret_cast<float2*>(&sbuf[w][2 * lane]) = make_float2(rx, ry);
    __syncwarp();

    // in-warp GEMV: lane computes out channel `lane`
    const float4* wrow = reinterpret_cast<const float4*>(sW2T + lane * 68);
    const float4* srow = reinterpret_cast<const float4*>(sbuf[w]);
    float h2 = 0.f;
#pragma unroll
    for (int k4 = 0; k4 < 16; k4++) {
        float4 s = srow[k4];
        float4 ww = wrow[k4];
        h2 += s.x * ww.x + s.y * ww.y + s.z * ww.z + s.w * ww.w;
    }
    g_h2h[d * OUTC + lane] = __float2half(h2 * dd);
}

// ---------------- layer-2 aggregation: warp per dst, gather --------------

__global__ __launch_bounds__(256) void k_agg2(const float* __restrict__ b2,
                                              float* __restrict__ out, int n) {
    int d = (blockIdx.x * blockDim.x + threadIdx.x) >> 5;
    int lane = threadIdx.x & 31;
    if (d >= n) return;
    int lo = g_off[d], hi = g_off[d + 1];
    float dd = g_dis[d];

    float acc = __half2float(g_h2h[d * OUTC + lane]);

    for (int jb = lo; jb < hi; jb += 32) {
        int myidx = (jb + lane < hi) ? g_csrc[jb + lane] : 0;
        int cnt = min(32, hi - jb);
        int kk = 0;
        for (; kk + 8 <= cnt; kk += 8) {
            int s0 = __shfl_sync(0xffffffffu, myidx, kk + 0);
            int s1 = __shfl_sync(0xffffffffu, myidx, kk + 1);
            int s2 = __shfl_sync(0xffffffffu, myidx, kk + 2);
            int s3 = __shfl_sync(0xffffffffu, myidx, kk + 3);
            int s4 = __shfl_sync(0xffffffffu, myidx, kk + 4);
            int s5 = __shfl_sync(0xffffffffu, myidx, kk + 5);
            int s6 = __shfl_sync(0xffffffffu, myidx, kk + 6);
            int s7 = __shfl_sync(0xffffffffu, myidx, kk + 7);
            float f0 = __half2float(g_h2h[s0 * OUTC + lane]);
            float f1 = __half2float(g_h2h[s1 * OUTC + lane]);
            float f2 = __half2float(g_h2h[s2 * OUTC + lane]);
            float f3 = __half2float(g_h2h[s3 * OUTC + lane]);
            float f4 = __half2float(g_h2h[s4 * OUTC + lane]);
            float f5 = __half2float(g_h2h[s5 * OUTC + lane]);
            float f6 = __half2float(g_h2h[s6 * OUTC + lane]);
            float f7 = __half2float(g_h2h[s7 * OUTC + lane]);
            acc += ((f0 + f1) + (f2 + f3)) + ((f4 + f5) + (f6 + f7));
        }
        for (; kk < cnt; kk++) {
            int s0 = __shfl_sync(0xffffffffu, myidx, kk);
            acc += __half2float(g_h2h[s0 * OUTC + lane]);
        }
    }

    out[d * OUTC + lane] = acc * dd + b2[lane];
}

// ---------------- launch (R11 fork-join schedule) ----------------

extern "C" void kernel_launch(void* const* d_in, const int* in_sizes, int n_in,
                              void* d_out, int out_size) {
    const float* x  = (const float*)d_in[0];
    const int*   ei = (const int*)  d_in[1];
    const float* W1 = (const float*)d_in[2];
    const float* b1 = (const float*)d_in[3];
    const float* W2 = (const float*)d_in[4];
    const float* b2 = (const float*)d_in[5];
    float* out = (float*)d_out;

    int N = in_sizes[0] / IN_CH;
    int E = in_sizes[1] / 2;
    int nb = (N + 255) / 256;

    // side stream + events, created once (first call is outside graph capture)
    static cudaStream_t s1 = nullptr;
    static cudaEvent_t eFork = nullptr, eJoin = nullptr;
    if (!s1) {
        cudaStreamCreateWithFlags(&s1, cudaStreamNonBlocking);
        cudaEventCreateWithFlags(&eFork, cudaEventDisableTiming);
        cudaEventCreateWithFlags(&eJoin, cudaEventDisableTiming);
    }

    const int T = 256;
    k_zero   <<<(N + T - 1) / T, T>>>(N);
    k_count  <<<(E + T - 1) / T, T>>>(ei, E);

    // fork: side stream runs dis + gemm1 (depends only on counts)
    cudaEventRecord(eFork, 0);
    cudaStreamWaitEvent(s1, eFork, 0);
    k_dis  <<<(N + T - 1) / T, T, 0, s1>>>(N);
    k_gemm1<<<(N + 127) / 128, 256, 0, s1>>>(x, W1, N);
    cudaEventRecord(eJoin, s1);

    // main stream: CSR offsets + scatter (concurrent with gemm1)
    k_scan1  <<<nb, 256>>>(N);
    k_scan2  <<<1, 512>>>(nb);
    k_scan3  <<<nb, 256>>>(N);
    k_scatter<<<(E + T - 1) / T, T>>>(ei, E);

    // join: fused aggregation needs both CSR and h1h
    cudaStreamWaitEvent(0, eJoin, 0);

    k_agg1f<<<(N * 32 + T - 1) / T, T>>>(b1, W2, N);
    k_agg2 <<<(N * 32 + T - 1) / T, T>>>(b2, out, N);
}

// round 15
// speedup vs baseline: 1.1361x; 1.1361x over previous
#include <cuda_runtime.h>
#include <cuda_bf16.h>
#include <cuda_fp16.h>
#include <cstdint>

// GCN 2-layer, CSR gather formulation with pre-scaled fp16 rows.
// R11 fork-join schedule; agg1->gemm2 interface is fp16 relu'd (g_r1h).

#define NMAX   100000
#define EMAX   1600000
#define IN_CH  128
#define HID    64
#define OUTC   32

typedef unsigned long long ull;

__device__ int    g_cnt[NMAX];           // in-degree (no self loop)
__device__ int    g_part[512];           // block partials -> inclusive prefix
__device__ int    g_off[NMAX + 1];       // CSR offsets
__device__ int    g_cur[NMAX];           // scatter cursors
__device__ int    g_csrc[EMAX];          // CSR src lists grouped by dst
__device__ float  g_dis[NMAX];           // deg^{-1/2} (deg incl self loop)
__device__ __half g_h1h[NMAX * HID];     // dis-scaled x@W1, fp16
__device__ __half g_r1h[NMAX * HID];     // relu(agg1), fp16 (gemm2 input)
__device__ __half g_h2h[NMAX * OUTC];    // dis-scaled relu(agg1)@W2, fp16

// packed dual-fp32 FMA (gemm2)
__device__ __forceinline__ void fma2(ull& acc, ull a, ull b) {
    asm("fma.rn.f32x2 %0, %1, %2, %0;" : "+l"(acc) : "l"(a), "l"(b));
}
__device__ __forceinline__ float unpack_sum(ull v) {
    float2 f;
    asm("mov.b64 {%0, %1}, %2;" : "=f"(f.x), "=f"(f.y) : "l"(v));
    return f.x + f.y;
}

__device__ __forceinline__ uint32_t to_tf32(float f) {
    uint32_t r;
    asm("cvt.rna.tf32.f32 %0, %1;" : "=r"(r) : "f"(f));
    return r;
}

__device__ __forceinline__ void mma_tf32(float* d, const uint32_t* a, const uint32_t* b) {
    asm("mma.sync.aligned.m16n8k8.row.col.f32.tf32.tf32.f32 "
        "{%0,%1,%2,%3}, {%4,%5,%6,%7}, {%8,%9}, {%0,%1,%2,%3};"
        : "+f"(d[0]), "+f"(d[1]), "+f"(d[2]), "+f"(d[3])
        : "r"(a[0]), "r"(a[1]), "r"(a[2]), "r"(a[3]), "r"(b[0]), "r"(b[1]));
}

// ---------------- CSR build ----------------

__global__ void k_zero(int n) {
    int i = blockIdx.x * blockDim.x + threadIdx.x;
    if (i < n) g_cnt[i] = 0;
}

__global__ void k_count(const int* __restrict__ ei, int E) {
    int e = blockIdx.x * blockDim.x + threadIdx.x;
    if (e < E) atomicAdd(&g_cnt[ei[E + e]], 1);
}

__global__ void k_dis(int n) {
    int i = blockIdx.x * blockDim.x + threadIdx.x;
    if (i < n) g_dis[i] = rsqrtf((float)(g_cnt[i] + 1));
}

// scan pass 1: per-block sums of g_cnt (256 per block)
__global__ __launch_bounds__(256) void k_scan1(int n) {
    __shared__ int s[256];
    int t = threadIdx.x;
    int i = blockIdx.x * 256 + t;
    s[t] = (i < n) ? g_cnt[i] : 0;
    __syncthreads();
#pragma unroll
    for (int st = 128; st > 0; st >>= 1) {
        if (t < st) s[t] += s[t + st];
        __syncthreads();
    }
    if (t == 0) g_part[blockIdx.x] = s[0];
}

// scan pass 2: single block 512 thr, warp-shuffle inclusive scan of partials
__global__ __launch_bounds__(512) void k_scan2(int nb) {
    __shared__ int warp_sum[16];
    int t = threadIdx.x;
    int lane = t & 31, w = t >> 5;
    int v = (t < nb) ? g_part[t] : 0;
#pragma unroll
    for (int ofs = 1; ofs < 32; ofs <<= 1) {
        int u = __shfl_up_sync(0xffffffffu, v, ofs);
        if (lane >= ofs) v += u;
    }
    if (lane == 31) warp_sum[w] = v;
    __syncthreads();
    if (w == 0) {
        int ws = (lane < 16) ? warp_sum[lane] : 0;
#pragma unroll
        for (int ofs = 1; ofs < 16; ofs <<= 1) {
            int u = __shfl_up_sync(0xffffffffu, ws, ofs);
            if (lane >= ofs) ws += u;
        }
        if (lane < 16) warp_sum[lane] = ws;
    }
    __syncthreads();
    if (w > 0) v += warp_sum[w - 1];
    g_part[t] = v;
}

// scan pass 3: offsets = block base + in-block exclusive scan
__global__ __launch_bounds__(256) void k_scan3(int n) {
    __shared__ int s[256];
    int t = threadIdx.x;
    int i = blockIdx.x * 256 + t;
    int c = (i < n) ? g_cnt[i] : 0;
    s[t] = c;
    __syncthreads();
#pragma unroll
    for (int ofs = 1; ofs < 256; ofs <<= 1) {
        int v = (t >= ofs) ? s[t - ofs] : 0;
        __syncthreads();
        s[t] += v;
        __syncthreads();
    }
    int basep = blockIdx.x ? g_part[blockIdx.x - 1] : 0;
    if (i < n) {
        int off = basep + s[t] - c;
        g_off[i] = off;
        g_cur[i] = off;
        if (i == n - 1) g_off[n] = basep + s[t];
    }
}

__global__ void k_scatter(const int* __restrict__ ei, int E) {
    int e = blockIdx.x * blockDim.x + threadIdx.x;
    if (e < E) {
        int s = ei[e];
        int d = ei[E + e];
        int pos = atomicAdd(&g_cur[d], 1);
        g_csrc[pos] = s;
    }
}

// ---------------- GEMM1 (tf32 tensor core): h1h = fp16(dis * x@W1) -------
// CTA: 128 nodes x 64 ch, K chunked by 32. 8 warps 4(M)x2(N), warp 32x32.

#define KCT 32

__global__ __launch_bounds__(256) void k_gemm1(const float* __restrict__ x,
                                               const float* __restrict__ W1,
                                               int n) {
    __shared__ uint32_t sA[8 * 4 * 32 * 4];   // 16 KB
    __shared__ uint32_t sB[8 * 4 * 32 * 2];   // 8 KB

    int tid = threadIdx.x;
    int lane = tid & 31;
    int wid = tid >> 5;
    int warp_m = wid & 3;
    int warp_n = wid >> 2;
    int base = blockIdx.x * 128;

    float acc[2][4][4];
#pragma unroll
    for (int fm = 0; fm < 2; fm++)
#pragma unroll
        for (int fn = 0; fn < 4; fn++)
#pragma unroll
            for (int r = 0; r < 4; r++) acc[fm][fn][r] = 0.f;

    for (int kc = 0; kc < IN_CH; kc += KCT) {
        __syncthreads();
#pragma unroll
        for (int i = 0; i < 4; i++) {
            int f = tid + 256 * i;
            int node = f >> 3;
            int q = f & 7;
            int gn = base + node;
            float4 v = make_float4(0.f, 0.f, 0.f, 0.f);
            if (gn < n) v = reinterpret_cast<const float4*>(x + gn * IN_CH + kc)[q];
            float vv[4] = {v.x, v.y, v.z, v.w};
            int mt = node >> 4, mm = node & 15;
#pragma unroll
            for (int j = 0; j < 4; j++) {
                int k = 4 * q + j;
                int kstep = k >> 3, kk = k & 7;
                int lt = ((mm & 7) << 2) | (kk & 3);
                int idx = (mm >> 3) | ((kk >> 2) << 1);
                sA[(((mt << 2) | kstep) << 7) + (lt << 2) + idx] = to_tf32(vv[j]);
            }
        }
#pragma unroll
        for (int i = 0; i < 2; i++) {
            int f = tid + 256 * i;
            int kr = f >> 4;
            int qc = f & 15;
            float4 w = reinterpret_cast<const float4*>(W1 + (kc + kr) * HID)[qc];
            float ww[4] = {w.x, w.y, w.z, w.w};
            int kstep = kr >> 3, kk = kr & 7;
#pragma unroll
            for (int j = 0; j < 4; j++) {
                int c = 4 * qc + j;
                int nt = c >> 3, nn = c & 7;
                int lt = (nn << 2) | (kk & 3);
                int idx = kk >> 2;
                sB[(((nt << 2) | kstep) << 6) + (lt << 1) + idx] = to_tf32(ww[j]);
            }
        }
        __syncthreads();

#pragma unroll
        for (int kstep = 0; kstep < 4; kstep++) {
            uint32_t a[2][4];
#pragma unroll
            for (int fm = 0; fm < 2; fm++) {
                int mt = warp_m * 2 + fm;
                uint4 v = *reinterpret_cast<const uint4*>(
                    sA + (((mt << 2) | kstep) << 7) + (lane << 2));
                a[fm][0] = v.x; a[fm][1] = v.y; a[fm][2] = v.z; a[fm][3] = v.w;
            }
            uint32_t b[4][2];
#pragma unroll
            for (int fn = 0; fn < 4; fn++) {
                int nt = warp_n * 4 + fn;
                uint2 v = *reinterpret_cast<const uint2*>(
                    sB + (((nt << 2) | kstep) << 6) + (lane << 1));
                b[fn][0] = v.x; b[fn][1] = v.y;
            }
#pragma unroll
            for (int fm = 0; fm < 2; fm++)
#pragma unroll
                for (int fn = 0; fn < 4; fn++)
                    mma_tf32(acc[fm][fn], a[fm], b[fn]);
        }
    }

    int g = lane >> 2, t4 = lane & 3;
#pragma unroll
    for (int fm = 0; fm < 2; fm++) {
#pragma unroll
        for (int r = 0; r < 2; r++) {
            int m = base + warp_m * 32 + fm * 16 + g + r * 8;
            if (m >= n) continue;
            float ds = g_dis[m];
#pragma unroll
            for (int fn = 0; fn < 4; fn++) {
                int nn = warp_n * 32 + fn * 8 + t4 * 2;
                float c0 = acc[fm][fn][2 * r] * ds;
                float c1 = acc[fm][fn][2 * r + 1] * ds;
                *reinterpret_cast<__half2*>(g_h1h + m * HID + nn) =
                    __floats2half2_rn(c0, c1);
            }
        }
    }
}

// ---------------- layer-1 aggregation: warp per dst, gather --------------
// writes fp16 relu'd result directly (gemm2 input)

__global__ __launch_bounds__(256) void k_agg1(const float* __restrict__ b1, int n) {
    int d = (blockIdx.x * blockDim.x + threadIdx.x) >> 5;
    int lane = threadIdx.x & 31;
    if (d >= n) return;
    int lo = g_off[d], hi = g_off[d + 1];
    float dd = g_dis[d];

    float2 acc = __half22float2(
        reinterpret_cast<const __half2*>(g_h1h + d * HID)[lane]);

    for (int jb = lo; jb < hi; jb += 32) {
        int myidx = (jb + lane < hi) ? g_csrc[jb + lane] : 0;
        int cnt = min(32, hi - jb);
        int kk = 0;
        for (; kk + 8 <= cnt; kk += 8) {
            int s0 = __shfl_sync(0xffffffffu, myidx, kk + 0);
            int s1 = __shfl_sync(0xffffffffu, myidx, kk + 1);
            int s2 = __shfl_sync(0xffffffffu, myidx, kk + 2);
            int s3 = __shfl_sync(0xffffffffu, myidx, kk + 3);
            int s4 = __shfl_sync(0xffffffffu, myidx, kk + 4);
            int s5 = __shfl_sync(0xffffffffu, myidx, kk + 5);
            int s6 = __shfl_sync(0xffffffffu, myidx, kk + 6);
            int s7 = __shfl_sync(0xffffffffu, myidx, kk + 7);
            __half2 v0 = reinterpret_cast<const __half2*>(g_h1h + s0 * HID)[lane];
            __half2 v1 = reinterpret_cast<const __half2*>(g_h1h + s1 * HID)[lane];
            __half2 v2 = reinterpret_cast<const __half2*>(g_h1h + s2 * HID)[lane];
            __half2 v3 = reinterpret_cast<const __half2*>(g_h1h + s3 * HID)[lane];
            __half2 v4 = reinterpret_cast<const __half2*>(g_h1h + s4 * HID)[lane];
            __half2 v5 = reinterpret_cast<const __half2*>(g_h1h + s5 * HID)[lane];
            __half2 v6 = reinterpret_cast<const __half2*>(g_h1h + s6 * HID)[lane];
            __half2 v7 = reinterpret_cast<const __half2*>(g_h1h + s7 * HID)[lane];
            float2 f0 = __half22float2(v0), f1 = __half22float2(v1);
            float2 f2 = __half22float2(v2), f3 = __half22float2(v3);
            float2 f4 = __half22float2(v4), f5 = __half22float2(v5);
            float2 f6 = __half22float2(v6), f7 = __half22float2(v7);
            acc.x += ((f0.x + f1.x) + (f2.x + f3.x)) + ((f4.x + f5.x) + (f6.x + f7.x));
            acc.y += ((f0.y + f1.y) + (f2.y + f3.y)) + ((f4.y + f5.y) + (f6.y + f7.y));
        }
        for (; kk < cnt; kk++) {
            int s0 = __shfl_sync(0xffffffffu, myidx, kk);
            float2 f0 = __half22float2(
                reinterpret_cast<const __half2*>(g_h1h + s0 * HID)[lane]);
            acc.x += f0.x;
            acc.y += f0.y;
        }
    }

    float2 bb = reinterpret_cast<const float2*>(b1)[lane];
    float rx = fmaxf(acc.x * dd + bb.x, 0.f);
    float ry = fmaxf(acc.y * dd + bb.y, 0.f);
    reinterpret_cast<__half2*>(g_r1h + d * HID)[lane] = __floats2half2_rn(rx, ry);
}

// ---------------- GEMM2: h2h = fp16(dis * r1h@W2) ------------------------
// 128 nodes x 32 ch / block, 256 thr, f32x2 K-pairing; input fp16 (relu'd).

__global__ __launch_bounds__(256) void k_gemm2(const float* __restrict__ W2, int n) {
    __shared__ float sx[128 * 66];
    __shared__ float sWp[(HID / 2) * 64];

    int tid = threadIdx.x;
    int base = blockIdx.x * 128;
    int ng = tid & 31;
    int cg = tid >> 5;

#pragma unroll
    for (int i = 0; i < 8; i++) {
        int idx = tid + 256 * i;
        int k = idx >> 5, c = idx & 31;
        sWp[(k >> 1) * 64 + c * 2 + (k & 1)] = W2[k * OUTC + c];
    }
#pragma unroll
    for (int i = 0; i < 8; i++) {
        int f = tid + 256 * i;
        int node = f >> 4;
        int q = f & 15;
        int gn = base + node;
        float4 v = make_float4(0.f, 0.f, 0.f, 0.f);
        if (gn < n) {
            uint2 hv = reinterpret_cast<const uint2*>(g_r1h + gn * HID)[q];
            __half2 h0 = *reinterpret_cast<const __half2*>(&hv.x);
            __half2 h1 = *reinterpret_cast<const __half2*>(&hv.y);
            float2 a = __half22float2(h0);
            float2 b = __half22float2(h1);
            v = make_float4(a.x, a.y, b.x, b.y);
        }
        float* r = sx + node * 66 + 4 * q;
        r[0] = v.x; r[1] = v.y; r[2] = v.z; r[3] = v.w;
    }
    __syncthreads();

    ull acc[4][4];
#pragma unroll
    for (int i = 0; i < 4; i++)
#pragma unroll
        for (int j = 0; j < 4; j++) acc[i][j] = 0ull;

#pragma unroll
    for (int k2 = 0; k2 < HID / 2; k2++) {
        ull xv0 = *reinterpret_cast<const ull*>(sx + ng * 66 + 2 * k2);
        ull xv1 = *reinterpret_cast<const ull*>(sx + (ng + 32) * 66 + 2 * k2);
        ull xv2 = *reinterpret_cast<const ull*>(sx + (ng + 64) * 66 + 2 * k2);
        ull xv3 = *reinterpret_cast<const ull*>(sx + (ng + 96) * 66 + 2 * k2);
        const ulonglong2* wr =
            reinterpret_cast<const ulonglong2*>(sWp + k2 * 64 + cg * 8);
        ulonglong2 wa = wr[0], wb = wr[1];
        fma2(acc[0][0], xv0, wa.x); fma2(acc[1][0], xv1, wa.x);
        fma2(acc[2][0], xv2, wa.x); fma2(acc[3][0], xv3, wa.x);
        fma2(acc[0][1], xv0, wa.y); fma2(acc[1][1], xv1, wa.y);
        fma2(acc[2][1], xv2, wa.y); fma2(acc[3][1], xv3, wa.y);
        fma2(acc[0][2], xv0, wb.x); fma2(acc[1][2], xv1, wb.x);
        fma2(acc[2][2], xv2, wb.x); fma2(acc[3][2], xv3, wb.x);
        fma2(acc[0][3], xv0, wb.y); fma2(acc[1][3], xv1, wb.y);
        fma2(acc[2][3], xv2, wb.y); fma2(acc[3][3], xv3, wb.y);
    }

#pragma unroll
    for (int i = 0; i < 4; i++) {
        int node = base + ng + 32 * i;
        if (node >= n) continue;
        float ds = g_dis[node];
        float r0 = unpack_sum(acc[i][0]) * ds, r1 = unpack_sum(acc[i][1]) * ds;
        float r2 = unpack_sum(acc[i][2]) * ds, r3 = unpack_sum(acc[i][3]) * ds;
        __half2* oh = reinterpret_cast<__half2*>(g_h2h + node * OUTC + cg * 4);
        oh[0] = __floats2half2_rn(r0, r1);
        oh[1] = __floats2half2_rn(r2, r3);
    }
}

// ---------------- layer-2 aggregation: warp per dst, gather --------------

__global__ __launch_bounds__(256) void k_agg2(const float* __restrict__ b2,
                                              float* __restrict__ out, int n) {
    int d = (blockIdx.x * blockDim.x + threadIdx.x) >> 5;
    int lane = threadIdx.x & 31;
    if (d >= n) return;
    int lo = g_off[d], hi = g_off[d + 1];
    float dd = g_dis[d];

    float acc = __half2float(g_h2h[d * OUTC + lane]);

    for (int jb = lo; jb < hi; jb += 32) {
        int myidx = (jb + lane < hi) ? g_csrc[jb + lane] : 0;
        int cnt = min(32, hi - jb);
        int kk = 0;
        for (; kk + 8 <= cnt; kk += 8) {
            int s0 = __shfl_sync(0xffffffffu, myidx, kk + 0);
            int s1 = __shfl_sync(0xffffffffu, myidx, kk + 1);
            int s2 = __shfl_sync(0xffffffffu, myidx, kk + 2);
            int s3 = __shfl_sync(0xffffffffu, myidx, kk + 3);
            int s4 = __shfl_sync(0xffffffffu, myidx, kk + 4);
            int s5 = __shfl_sync(0xffffffffu, myidx, kk + 5);
            int s6 = __shfl_sync(0xffffffffu, myidx, kk + 6);
            int s7 = __shfl_sync(0xffffffffu, myidx, kk + 7);
            float f0 = __half2float(g_h2h[s0 * OUTC + lane]);
            float f1 = __half2float(g_h2h[s1 * OUTC + lane]);
            float f2 = __half2float(g_h2h[s2 * OUTC + lane]);
            float f3 = __half2float(g_h2h[s3 * OUTC + lane]);
            float f4 = __half2float(g_h2h[s4 * OUTC + lane]);
            float f5 = __half2float(g_h2h[s5 * OUTC + lane]);
            float f6 = __half2float(g_h2h[s6 * OUTC + lane]);
            float f7 = __half2float(g_h2h[s7 * OUTC + lane]);
            acc += ((f0 + f1) + (f2 + f3)) + ((f4 + f5) + (f6 + f7));
        }
        for (; kk < cnt; kk++) {
            int s0 = __shfl_sync(0xffffffffu, myidx, kk);
            acc += __half2float(g_h2h[s0 * OUTC + lane]);
        }
    }

    out[d * OUTC + lane] = acc * dd + b2[lane];
}

// ---------------- launch (R11 fork-join schedule) ----------------

extern "C" void kernel_launch(void* const* d_in, const int* in_sizes, int n_in,
                              void* d_out, int out_size) {
    const float* x  = (const float*)d_in[0];
    const int*   ei = (const int*)  d_in[1];
    const float* W1 = (const float*)d_in[2];
    const float* b1 = (const float*)d_in[3];
    const float* W2 = (const float*)d_in[4];
    const float* b2 = (const float*)d_in[5];
    float* out = (float*)d_out;

    int N = in_sizes[0] / IN_CH;
    int E = in_sizes[1] / 2;
    int nb = (N + 255) / 256;

    // side stream + events, created once (first call is outside graph capture)
    static cudaStream_t s1 = nullptr;
    static cudaEvent_t eFork = nullptr, eJoin = nullptr;
    if (!s1) {
        cudaStreamCreateWithFlags(&s1, cudaStreamNonBlocking);
        cudaEventCreateWithFlags(&eFork, cudaEventDisableTiming);
        cudaEventCreateWithFlags(&eJoin, cudaEventDisableTiming);
    }

    const int T = 256;
    k_zero   <<<(N + T - 1) / T, T>>>(N);
    k_count  <<<(E + T - 1) / T, T>>>(ei, E);

    // fork: side stream runs dis + gemm1 (depends only on counts)
    cudaEventRecord(eFork, 0);
    cudaStreamWaitEvent(s1, eFork, 0);
    k_dis  <<<(N + T - 1) / T, T, 0, s1>>>(N);
    k_gemm1<<<(N + 127) / 128, 256, 0, s1>>>(x, W1, N);
    cudaEventRecord(eJoin, s1);

    // main stream: CSR offsets + scatter (concurrent with gemm1)
    k_scan1  <<<nb, 256>>>(N);
    k_scan2  <<<1, 512>>>(nb);
    k_scan3  <<<nb, 256>>>(N);
    k_scatter<<<(E + T - 1) / T, T>>>(ei, E);

    // join: aggregation needs both CSR and h1h
    cudaStreamWaitEvent(0, eJoin, 0);

    k_agg1 <<<(N * 32 + T - 1) / T, T>>>(b1, N);
    k_gemm2<<<(N + 127) / 128, 256>>>(W2, N);
    k_agg2 <<<(N * 32 + T - 1) / T, T>>>(b2, out, N);
}